// round 1
// baseline (speedup 1.0000x reference)
#include <cuda_runtime.h>

#define NBODY      8192
#define BLOCK      256
#define NSPLIT     16
#define JCHUNK     (NBODY / NSPLIT)   // 512
#define SOFT2      (0.01f * 0.01f)

__global__ void zero_out_kernel(float* out, int n) {
    int idx = blockIdx.x * blockDim.x + threadIdx.x;
    if (idx < n) out[idx] = 0.0f;
}

__global__ __launch_bounds__(BLOCK)
void nbody_kernel(const float* __restrict__ pos,
                  const float* __restrict__ mass,
                  float* __restrict__ out) {
    const int i = blockIdx.x * BLOCK + threadIdx.x;

    const float xi = pos[3 * i + 0];
    const float yi = pos[3 * i + 1];
    const float zi = pos[3 * i + 2];

    float ax = 0.0f, ay = 0.0f, az = 0.0f;

    __shared__ float4 sh[BLOCK];

    const int j0 = blockIdx.y * JCHUNK;

    for (int tile = 0; tile < JCHUNK; tile += BLOCK) {
        const int j = j0 + tile + threadIdx.x;
        sh[threadIdx.x] = make_float4(pos[3 * j + 0],
                                      pos[3 * j + 1],
                                      pos[3 * j + 2],
                                      mass[j]);
        __syncthreads();

        #pragma unroll 16
        for (int k = 0; k < BLOCK; k++) {
            const float4 p = sh[k];            // warp-broadcast LDS.128
            const float dx = p.x - xi;
            const float dy = p.y - yi;
            const float dz = p.z - zi;
            float d2 = SOFT2;
            d2 = fmaf(dx, dx, d2);
            d2 = fmaf(dy, dy, d2);
            d2 = fmaf(dz, dz, d2);
            const float inv  = rsqrtf(d2);
            const float inv2 = inv * inv;
            const float w    = p.w * inv2 * inv;   // m_j * d2^(-3/2)
            ax = fmaf(w, dx, ax);
            ay = fmaf(w, dy, ay);
            az = fmaf(w, dz, az);
        }
        __syncthreads();
    }

    atomicAdd(&out[3 * i + 0], ax);
    atomicAdd(&out[3 * i + 1], ay);
    atomicAdd(&out[3 * i + 2], az);
}

extern "C" void kernel_launch(void* const* d_in, const int* in_sizes, int n_in,
                              void* d_out, int out_size) {
    const float* pos  = (const float*)d_in[0];   // (8192, 3) float32
    const float* mass = (const float*)d_in[1];   // (8192,)   float32
    float* out        = (float*)d_out;           // (8192, 3) float32

    zero_out_kernel<<<(NBODY * 3 + 255) / 256, 256>>>(out, NBODY * 3);

    dim3 grid(NBODY / BLOCK, NSPLIT);
    nbody_kernel<<<grid, BLOCK>>>(pos, mass, out);
}